// round 3
// baseline (speedup 1.0000x reference)
#include <cuda_runtime.h>
#include <math.h>

#define Bx 4
#define Sx 128
#define Dx 256
#define Hx 8

static __device__ float  g_V [Bx*Sx*Dx];     // V = x@Wv.T + bv
static __device__ float  g_AO[Bx*Sx*Dx];     // attention output (pre-Wo)
static __device__ float  g_AB[Bx*Hx*Sx*6];   // per (b,h,i): A1,B1,A2,B2,A3,B3
static __device__ float4 g_CK[Bx*Hx*Sx];     // per (b,h,j): cos(k1..k3), pad

// ---------------------------------------------------------------------------
// GEMM core: C[m0+m][n0+n] = sum_k A[m][k]*B[n][k] + bias[n], K=256 (NT).
// Tile 16m x 32n, 256 threads, 1m x 2n per thread, acc=2, ~30 regs.
// Per warp-k4: 3 LDS.128 (XOR-swizzled, <=2 crossbar cyc each) + 8 FFMA.
// smem: As 16x64 f4 (16KB) + Bs 32x64 f4 (32KB) = 48KB exactly.
// ---------------------------------------------------------------------------
__device__ __forceinline__ void gemm16x32(
    const float4* __restrict__ A4, const float4* __restrict__ B4,
    const float* __restrict__ bias, float* __restrict__ C,
    int m0, int n0, float4* sm)
{
    float4* As = sm;          // [16][64], col ^= (row&7)
    float4* Bs = sm + 1024;   // [32][64], col ^= (row&7)
    const int tid = threadIdx.x;

#pragma unroll
    for (int t = 0; t < 4; t++) {
        const int idx = tid + t*256, r = idx >> 6, c = idx & 63;
        As[r*64 + (c ^ (r & 7))] = A4[(m0 + r)*64 + c];
    }
#pragma unroll
    for (int t = 0; t < 8; t++) {
        const int idx = tid + t*256, r = idx >> 6, c = idx & 63;
        Bs[r*64 + (c ^ (r & 7))] = B4[(n0 + r)*64 + c];
    }
    __syncthreads();

    const int ml = tid & 15;
    const int n  = (tid >> 4) << 1;
    const float4* ap  = As + ml*64;      const int ax  = ml & 7;
    const float4* bp0 = Bs + n*64;       const int bx0 = n & 7;
    const float4* bp1 = Bs + (n + 1)*64; const int bx1 = (n + 1) & 7;

    float acc0 = 0.f, acc1 = 0.f;
#pragma unroll 16
    for (int k4 = 0; k4 < 64; k4++) {
        const float4 a  = ap [k4 ^ ax ];
        const float4 b0 = bp0[k4 ^ bx0];
        const float4 b1 = bp1[k4 ^ bx1];
        acc0 = fmaf(a.x, b0.x, acc0);
        acc0 = fmaf(a.y, b0.y, acc0);
        acc0 = fmaf(a.z, b0.z, acc0);
        acc0 = fmaf(a.w, b0.w, acc0);
        acc1 = fmaf(a.x, b1.x, acc1);
        acc1 = fmaf(a.y, b1.y, acc1);
        acc1 = fmaf(a.z, b1.z, acc1);
        acc1 = fmaf(a.w, b1.w, acc1);
    }

    float2 o;
    o.x = acc0 + bias[n0 + n];
    o.y = acc1 + bias[n0 + n + 1];
    *(float2*)&C[(m0 + ml)*256 + n0 + n] = o;
}

// ---------------------------------------------------------------------------
// Q/K features. Block = (b, 4 s-rows), 256 threads = 8 warps (warp = head).
// score(i,j) = prod_{w=1..3}( cos(th_w)cos(q_iw) - sin(th_w)sin(q_iw)cos(k_jw) )
// ---------------------------------------------------------------------------
__device__ void feat_body(
    const float* __restrict__ x,
    const float* __restrict__ Wq, const float* __restrict__ bq,
    const float* __restrict__ Wk, const float* __restrict__ bk,
    const float* __restrict__ ap, int bid, float* smem)
{
    float (*xs)[256] = (float(*)[256])smem;
    const int b  = bid >> 5;
    const int s0 = (bid & 31) << 2;
    const int tid = threadIdx.x;

    for (int t = tid; t < 1024; t += 256)
        xs[t >> 8][t & 255] = x[(b*Sx + s0 + (t >> 8))*Dx + (t & 255)];
    __syncthreads();

    const int h = tid >> 5, lane = tid & 31;
    float acc[4][8];
#pragma unroll
    for (int s = 0; s < 4; s++)
#pragma unroll
        for (int o = 0; o < 8; o++) acc[s][o] = 0.f;

    const float* wq = Wq + (h*32)*Dx;
    const float* wk = Wk + (h*32)*Dx;

#pragma unroll
    for (int c = 0; c < 8; c++) {
        const int d = lane + (c << 5);
        const float x0 = xs[0][d], x1 = xs[1][d], x2 = xs[2][d], x3 = xs[3][d];
#pragma unroll
        for (int o = 0; o < 4; o++) {
            const float wv = wq[o*Dx + d];
            acc[0][o] = fmaf(x0, wv, acc[0][o]);
            acc[1][o] = fmaf(x1, wv, acc[1][o]);
            acc[2][o] = fmaf(x2, wv, acc[2][o]);
            acc[3][o] = fmaf(x3, wv, acc[3][o]);
        }
#pragma unroll
        for (int o = 0; o < 4; o++) {
            const float wv = wk[o*Dx + d];
            acc[0][4+o] = fmaf(x0, wv, acc[0][4+o]);
            acc[1][4+o] = fmaf(x1, wv, acc[1][4+o]);
            acc[2][4+o] = fmaf(x2, wv, acc[2][4+o]);
            acc[3][4+o] = fmaf(x3, wv, acc[3][4+o]);
        }
    }

#pragma unroll
    for (int s = 0; s < 4; s++)
#pragma unroll
        for (int o = 0; o < 8; o++) {
            float v = acc[s][o];
            v += __shfl_xor_sync(0xffffffffu, v, 16);
            v += __shfl_xor_sync(0xffffffffu, v, 8);
            v += __shfl_xor_sync(0xffffffffu, v, 4);
            v += __shfl_xor_sync(0xffffffffu, v, 2);
            v += __shfl_xor_sync(0xffffffffu, v, 1);
            acc[s][o] = v;
        }

    if (lane < 8) {
        const int sp = lane >> 1;
        const int side = lane & 1;
        const float* bias = side ? bk : bq;
        float vals[4];
#pragma unroll
        for (int wv = 0; wv < 4; wv++)
            vals[wv] = acc[sp][side*4 + wv] + bias[h*32 + wv];

        const float mn = fminf(fminf(vals[0], vals[1]), fminf(vals[2], vals[3]));
        const float mx = fmaxf(fmaxf(vals[0], vals[1]), fmaxf(vals[2], vals[3]));
        const float sc = 3.14159265358979323846f / (mx - mn + 1e-8f);
        const int idx = (b*Hx + h)*Sx + s0 + sp;

        if (side == 0) {
#pragma unroll
            for (int wv = 1; wv < 4; wv++) {
                const float ang = (vals[wv] - mn) * sc;
                float sn, cs;
                sincosf(ang, &sn, &cs);
                const float th = ap[wv];
                g_AB[idx*6 + (wv-1)*2 + 0] = cosf(th) * cs;
                g_AB[idx*6 + (wv-1)*2 + 1] = sinf(th) * sn;
            }
        } else {
            float c1 = cosf((vals[1] - mn) * sc);
            float c2 = cosf((vals[2] - mn) * sc);
            float c3 = cosf((vals[3] - mn) * sc);
            g_CK[idx] = make_float4(c1, c2, c3, 0.f);
        }
    }
}

// ---------------------------------------------------------------------------
// Kernel 1: V-GEMM (256 blocks) + qk features (128 blocks), 256 thr each.
// ---------------------------------------------------------------------------
__global__ void __launch_bounds__(256) k1_feat_vgemm(
    const float* __restrict__ x,
    const float* __restrict__ Wq, const float* __restrict__ bq,
    const float* __restrict__ Wk, const float* __restrict__ bk,
    const float* __restrict__ ap,
    const float* __restrict__ Wv, const float* __restrict__ bv)
{
    __shared__ float4 sm[3072];   // 48KB
    const int bx = blockIdx.x;
    if (bx < 256) {
        gemm16x32((const float4*)x, (const float4*)Wv, bv, g_V,
                  (bx >> 3) << 4, (bx & 7) << 5, sm);
    } else {
        feat_body(x, Wq, bq, Wk, bk, ap, bx - 256, (float*)sm);
    }
}

// ---------------------------------------------------------------------------
// Kernel 2: attention. 128 blocks = (bh, 32-row i-group), 256 threads.
// Phase 1: each exp computed once -> E[j][i] (padded), per-i sums.
// Phase 2: o[i][d4] = sum_j E[j][i] * V[j][d4], then scale by 1/sum.
// Scores bounded (|s|<=1, *0.177) -> no max subtraction needed.
// ---------------------------------------------------------------------------
__global__ void __launch_bounds__(256) attn_kernel()
{
    const int bx = blockIdx.x;
    const int ig = bx & 3;
    const int bh = bx >> 2;
    const int b = bh >> 3, h = bh & 7;

    __shared__ float4 Vs[1024];      // [j][p], p = d4 group 0..7
    __shared__ float4 CKs[128];
    __shared__ float  E[128*33];     // [j][il], pad 33
    __shared__ float  Psum[32*9];    // [il][jg], pad 9
    __shared__ float  Sinv[32];

    const int tid = threadIdx.x;
    const float4* V4 = (const float4*)g_V;
#pragma unroll
    for (int t = 0; t < 4; t++) {
        const int idx = tid + (t << 8);
        const int j = idx >> 3, p = idx & 7;
        Vs[idx] = V4[(b*Sx + j)*64 + h*8 + p];
    }
    if (tid < 128) CKs[tid] = g_CK[bh*Sx + tid];
    __syncthreads();

    const int il = tid & 31;
    const int i  = (ig << 5) + il;

    // phase 1: jg = tid>>5 handles 16 j's
    {
        const int jg = tid >> 5;
        const float* ab = &g_AB[(bh*Sx + i)*6];
        const float A1 = ab[0], B1 = ab[1];
        const float A2 = ab[2], B2 = ab[3];
        const float A3 = ab[4], B3 = ab[5];
        const float SCALE = 0.17677669529663687f; // 1/sqrt(32)
        float s = 0.f;
#pragma unroll
        for (int jj = 0; jj < 16; jj++) {
            const int j = (jg << 4) + jj;
            const float4 ck = CKs[j];
            const float sc = (A1 - B1*ck.x) * (A2 - B2*ck.y) * (A3 - B3*ck.z);
            const float e = __expf(sc * SCALE);
            E[j*33 + il] = e;
            s += e;
        }
        Psum[il*9 + jg] = s;
    }
    __syncthreads();
    if (tid < 32) {
        float s = 0.f;
#pragma unroll
        for (int jg = 0; jg < 8; jg++) s += Psum[tid*9 + jg];
        Sinv[tid] = 1.0f / s;
    }
    __syncthreads();

    // phase 2: p = tid>>5 owns one float4 dim-group (single-address V loads)
    {
        const int p = tid >> 5;
        float4 o = make_float4(0.f, 0.f, 0.f, 0.f);
#pragma unroll 8
        for (int j = 0; j < 128; j++) {
            const float e = E[j*33 + il];
            const float4 v = Vs[(j << 3) + p];
            o.x = fmaf(e, v.x, o.x);
            o.y = fmaf(e, v.y, o.y);
            o.z = fmaf(e, v.z, o.z);
            o.w = fmaf(e, v.w, o.w);
        }
        const float inv = Sinv[il];
        o.x *= inv; o.y *= inv; o.z *= inv; o.w *= inv;
        ((float4*)g_AO)[(b*Sx + i)*64 + h*8 + p] = o;
    }
}

// ---------------------------------------------------------------------------
// Kernel 3: out = g_AO @ Wo.T + bo  (256 blocks)
// ---------------------------------------------------------------------------
__global__ void __launch_bounds__(256) k3_ogemm(
    const float* __restrict__ Wo, const float* __restrict__ bo,
    float* __restrict__ out)
{
    __shared__ float4 sm[3072];
    const int bx = blockIdx.x;
    gemm16x32((const float4*)g_AO, (const float4*)Wo, bo, out,
              (bx >> 3) << 4, (bx & 7) << 5, sm);
}

// ---------------------------------------------------------------------------
extern "C" void kernel_launch(void* const* d_in, const int* in_sizes, int n_in,
                              void* d_out, int out_size)
{
    const float* x  = (const float*)d_in[0];
    const float* Wq = (const float*)d_in[1];
    const float* bq = (const float*)d_in[2];
    const float* Wk = (const float*)d_in[3];
    const float* bk = (const float*)d_in[4];
    const float* Wv = (const float*)d_in[5];
    const float* bv = (const float*)d_in[6];
    const float* Wo = (const float*)d_in[7];
    const float* bo = (const float*)d_in[8];
    const float* ap = (const float*)d_in[9];
    float* out = (float*)d_out;

    k1_feat_vgemm<<<384, 256>>>(x, Wq, bq, Wk, bk, ap, Wv, bv);
    attn_kernel<<<128, 256>>>();
    k3_ogemm<<<256, 256>>>(Wo, bo, out);
}

// round 4
// speedup vs baseline: 1.2090x; 1.2090x over previous
#include <cuda_runtime.h>
#include <math.h>

#define Bx 4
#define Sx 128
#define Dx 256
#define Hx 8

static __device__ float  g_V [Bx*Sx*Dx];     // V = x@Wv.T + bv
static __device__ float  g_AO[Bx*Sx*Dx];     // attention output (pre-Wo)
static __device__ float  g_AB[Bx*Hx*Sx*6];   // per (b,h,i): A1,B1,A2,B2,A3,B3
static __device__ float4 g_CK[Bx*Hx*Sx];     // per (b,h,j): cos(k1..k3), pad

// ---------------------------------------------------------------------------
// GEMM core: C[m0+m][n0+n] = sum_k A[m][k]*B[n][k] + bias[n], K=256 (NT).
// 32m x 32n tile, 256 threads, 2m x 2n micro-tile, K chunked by 128.
// A smem row-major (a-loads: 2-addr broadcast, conflict-free, no swizzle).
// B smem transposed BsT[k][n] pad 34 (b-loads: lane-consecutive float2).
// Transpose STS conflict-free: bank = 8c + r covers 0..31.
// Inner iter: 2 LDS.128 + 4 LDS.64 + 16 FFMA, all offsets immediate.
// ---------------------------------------------------------------------------
__device__ __forceinline__ void gemm32x32(
    const float4* __restrict__ A4, const float4* __restrict__ B4,
    const float* __restrict__ bias, float* __restrict__ C,
    int m0, int n0, float* sm /* >= 8448 floats (33KB) */)
{
    float4* As  = (float4*)sm;     // [32 m][32 k4] float4 = 16KB
    float*  BsT = sm + 4096;       // [128 k][34] floats  = 17KB

    const int tid = threadIdx.x;
    const int tx  = tid & 15;      // n/2
    const int ty  = tid >> 4;      // m/2

    float acc00 = 0.f, acc01 = 0.f, acc10 = 0.f, acc11 = 0.f;

    const float4* ar0 = As + (ty*2    )*32;
    const float4* ar1 = As + (ty*2 + 1)*32;
    const float*  bp  = BsT + (tx << 1);

    for (int kc = 0; kc < 2; kc++) {
        // --- load A chunk, coalesced, no transpose ---
#pragma unroll
        for (int t = 0; t < 4; t++) {
            const int g = tid + (t << 8);
            const int r = g >> 5, c = g & 31;
            As[(r << 5) + c] = A4[(m0 + r)*64 + (kc << 5) + c];
        }
        // --- load B chunk, transposed; lane decomposition: bank = 8c + r ---
#pragma unroll
        for (int t = 0; t < 4; t++) {
            const int g    = tid + (t << 8);
            const int lane = g & 31;
            const int r = (lane & 7) + (((g >> 5) & 3) << 3);   // n row 0..31
            const int c = (lane >> 3) + ((g >> 7) << 2);        // k4  0..31
            const float4 bv = B4[(n0 + r)*64 + (kc << 5) + c];
            const int k = c << 2;
            BsT[(k + 0)*34 + r] = bv.x;
            BsT[(k + 1)*34 + r] = bv.y;
            BsT[(k + 2)*34 + r] = bv.z;
            BsT[(k + 3)*34 + r] = bv.w;
        }
        __syncthreads();

#pragma unroll 16
        for (int k4 = 0; k4 < 32; k4++) {
            const float4 a0 = ar0[k4];
            const float4 a1 = ar1[k4];
            const float2 b0 = *(const float2*)&bp[(k4*4 + 0)*34];
            const float2 b1 = *(const float2*)&bp[(k4*4 + 1)*34];
            const float2 b2 = *(const float2*)&bp[(k4*4 + 2)*34];
            const float2 b3 = *(const float2*)&bp[(k4*4 + 3)*34];
            acc00 = fmaf(a0.x, b0.x, acc00); acc01 = fmaf(a0.x, b0.y, acc01);
            acc10 = fmaf(a1.x, b0.x, acc10); acc11 = fmaf(a1.x, b0.y, acc11);
            acc00 = fmaf(a0.y, b1.x, acc00); acc01 = fmaf(a0.y, b1.y, acc01);
            acc10 = fmaf(a1.y, b1.x, acc10); acc11 = fmaf(a1.y, b1.y, acc11);
            acc00 = fmaf(a0.z, b2.x, acc00); acc01 = fmaf(a0.z, b2.y, acc01);
            acc10 = fmaf(a1.z, b2.x, acc10); acc11 = fmaf(a1.z, b2.y, acc11);
            acc00 = fmaf(a0.w, b3.x, acc00); acc01 = fmaf(a0.w, b3.y, acc01);
            acc10 = fmaf(a1.w, b3.x, acc10); acc11 = fmaf(a1.w, b3.y, acc11);
        }
        __syncthreads();
    }

    const int m = m0 + ty*2, n = n0 + tx*2;
    const float2 b2 = *(const float2*)&bias[n];
    *(float2*)&C[ m     *256 + n] = make_float2(acc00 + b2.x, acc01 + b2.y);
    *(float2*)&C[(m + 1)*256 + n] = make_float2(acc10 + b2.x, acc11 + b2.y);
}

// ---------------------------------------------------------------------------
// Q/K features. Block = (b, 4 s-rows), 256 threads = 8 warps (warp = head).
// score(i,j) = prod_{w=1..3}( cos(th_w)cos(q_iw) - sin(th_w)sin(q_iw)cos(k_jw) )
// ---------------------------------------------------------------------------
__device__ void feat_body(
    const float* __restrict__ x,
    const float* __restrict__ Wq, const float* __restrict__ bq,
    const float* __restrict__ Wk, const float* __restrict__ bk,
    const float* __restrict__ ap, int bid, float* smem)
{
    float (*xs)[256] = (float(*)[256])smem;
    const int b  = bid >> 5;
    const int s0 = (bid & 31) << 2;
    const int tid = threadIdx.x;

    for (int t = tid; t < 1024; t += 256)
        xs[t >> 8][t & 255] = x[(b*Sx + s0 + (t >> 8))*Dx + (t & 255)];
    __syncthreads();

    const int h = tid >> 5, lane = tid & 31;
    float acc[4][8];
#pragma unroll
    for (int s = 0; s < 4; s++)
#pragma unroll
        for (int o = 0; o < 8; o++) acc[s][o] = 0.f;

    const float* wq = Wq + (h*32)*Dx;
    const float* wk = Wk + (h*32)*Dx;

#pragma unroll
    for (int c = 0; c < 8; c++) {
        const int d = lane + (c << 5);
        const float x0 = xs[0][d], x1 = xs[1][d], x2 = xs[2][d], x3 = xs[3][d];
#pragma unroll
        for (int o = 0; o < 4; o++) {
            const float wv = wq[o*Dx + d];
            acc[0][o] = fmaf(x0, wv, acc[0][o]);
            acc[1][o] = fmaf(x1, wv, acc[1][o]);
            acc[2][o] = fmaf(x2, wv, acc[2][o]);
            acc[3][o] = fmaf(x3, wv, acc[3][o]);
        }
#pragma unroll
        for (int o = 0; o < 4; o++) {
            const float wv = wk[o*Dx + d];
            acc[0][4+o] = fmaf(x0, wv, acc[0][4+o]);
            acc[1][4+o] = fmaf(x1, wv, acc[1][4+o]);
            acc[2][4+o] = fmaf(x2, wv, acc[2][4+o]);
            acc[3][4+o] = fmaf(x3, wv, acc[3][4+o]);
        }
    }

#pragma unroll
    for (int s = 0; s < 4; s++)
#pragma unroll
        for (int o = 0; o < 8; o++) {
            float v = acc[s][o];
            v += __shfl_xor_sync(0xffffffffu, v, 16);
            v += __shfl_xor_sync(0xffffffffu, v, 8);
            v += __shfl_xor_sync(0xffffffffu, v, 4);
            v += __shfl_xor_sync(0xffffffffu, v, 2);
            v += __shfl_xor_sync(0xffffffffu, v, 1);
            acc[s][o] = v;
        }

    if (lane < 8) {
        const int sp = lane >> 1;
        const int side = lane & 1;
        const float* bias = side ? bk : bq;
        float vals[4];
#pragma unroll
        for (int wv = 0; wv < 4; wv++)
            vals[wv] = acc[sp][side*4 + wv] + bias[h*32 + wv];

        const float mn = fminf(fminf(vals[0], vals[1]), fminf(vals[2], vals[3]));
        const float mx = fmaxf(fmaxf(vals[0], vals[1]), fmaxf(vals[2], vals[3]));
        const float sc = 3.14159265358979323846f / (mx - mn + 1e-8f);
        const int idx = (b*Hx + h)*Sx + s0 + sp;

        if (side == 0) {
#pragma unroll
            for (int wv = 1; wv < 4; wv++) {
                const float ang = (vals[wv] - mn) * sc;
                float sn, cs;
                sincosf(ang, &sn, &cs);
                const float th = ap[wv];
                g_AB[idx*6 + (wv-1)*2 + 0] = cosf(th) * cs;
                g_AB[idx*6 + (wv-1)*2 + 1] = sinf(th) * sn;
            }
        } else {
            float c1 = cosf((vals[1] - mn) * sc);
            float c2 = cosf((vals[2] - mn) * sc);
            float c3 = cosf((vals[3] - mn) * sc);
            g_CK[idx] = make_float4(c1, c2, c3, 0.f);
        }
    }
}

// ---------------------------------------------------------------------------
// Kernel 1: V-GEMM (128 blocks) + qk features (128 blocks), 256 thr each.
// ---------------------------------------------------------------------------
__global__ void __launch_bounds__(256) k1_feat_vgemm(
    const float* __restrict__ x,
    const float* __restrict__ Wq, const float* __restrict__ bq,
    const float* __restrict__ Wk, const float* __restrict__ bk,
    const float* __restrict__ ap,
    const float* __restrict__ Wv, const float* __restrict__ bv)
{
    __shared__ float sm[8448];    // 33KB
    const int bx = blockIdx.x;
    if (bx < 128) {
        gemm32x32((const float4*)x, (const float4*)Wv, bv, g_V,
                  (bx >> 3) << 5, (bx & 7) << 5, sm);
    } else {
        feat_body(x, Wq, bq, Wk, bk, ap, bx - 128, sm);
    }
}

// ---------------------------------------------------------------------------
// Kernel 2: attention. 128 blocks = (bh, 32-row i-group), 256 threads.
// Phase 1: each exp computed once -> E[j][i] (padded), per-i sums.
// Phase 2: o[i][d4] = sum_j E[j][i] * V[j][d4], then scale by 1/sum.
// Scores bounded (|s|<=0.177) -> no max subtraction needed.
// ---------------------------------------------------------------------------
__global__ void __launch_bounds__(256) attn_kernel()
{
    const int bx = blockIdx.x;
    const int ig = bx & 3;
    const int bh = bx >> 2;
    const int b = bh >> 3, h = bh & 7;

    __shared__ float4 Vs[1024];      // [j][p], p = d4 group 0..7
    __shared__ float4 CKs[128];
    __shared__ float  E[128*33];     // [j][il], pad 33
    __shared__ float  Psum[32*9];    // [il][jg], pad 9
    __shared__ float  Sinv[32];

    const int tid = threadIdx.x;
    const float4* V4 = (const float4*)g_V;
#pragma unroll
    for (int t = 0; t < 4; t++) {
        const int idx = tid + (t << 8);
        const int j = idx >> 3, p = idx & 7;
        Vs[idx] = V4[(b*Sx + j)*64 + h*8 + p];
    }
    if (tid < 128) CKs[tid] = g_CK[bh*Sx + tid];
    __syncthreads();

    const int il = tid & 31;
    const int i  = (ig << 5) + il;

    // phase 1: jg = tid>>5 handles 16 j's
    {
        const int jg = tid >> 5;
        const float* ab = &g_AB[(bh*Sx + i)*6];
        const float A1 = ab[0], B1 = ab[1];
        const float A2 = ab[2], B2 = ab[3];
        const float A3 = ab[4], B3 = ab[5];
        const float SCALE = 0.17677669529663687f; // 1/sqrt(32)
        float s = 0.f;
#pragma unroll
        for (int jj = 0; jj < 16; jj++) {
            const int j = (jg << 4) + jj;
            const float4 ck = CKs[j];
            const float sc = (A1 - B1*ck.x) * (A2 - B2*ck.y) * (A3 - B3*ck.z);
            const float e = __expf(sc * SCALE);
            E[j*33 + il] = e;
            s += e;
        }
        Psum[il*9 + jg] = s;
    }
    __syncthreads();
    if (tid < 32) {
        float s = 0.f;
#pragma unroll
        for (int jg = 0; jg < 8; jg++) s += Psum[tid*9 + jg];
        Sinv[tid] = 1.0f / s;
    }
    __syncthreads();

    // phase 2: p = tid>>5 owns one float4 dim-group (broadcast V loads)
    {
        const int p = tid >> 5;
        float4 o = make_float4(0.f, 0.f, 0.f, 0.f);
#pragma unroll 8
        for (int j = 0; j < 128; j++) {
            const float e = E[j*33 + il];
            const float4 v = Vs[(j << 3) + p];
            o.x = fmaf(e, v.x, o.x);
            o.y = fmaf(e, v.y, o.y);
            o.z = fmaf(e, v.z, o.z);
            o.w = fmaf(e, v.w, o.w);
        }
        const float inv = Sinv[il];
        o.x *= inv; o.y *= inv; o.z *= inv; o.w *= inv;
        ((float4*)g_AO)[(b*Sx + i)*64 + h*8 + p] = o;
    }
}

// ---------------------------------------------------------------------------
// Kernel 3: out = g_AO @ Wo.T + bo  (128 blocks)
// ---------------------------------------------------------------------------
__global__ void __launch_bounds__(256) k3_ogemm(
    const float* __restrict__ Wo, const float* __restrict__ bo,
    float* __restrict__ out)
{
    __shared__ float sm[8448];
    const int bx = blockIdx.x;
    gemm32x32((const float4*)g_AO, (const float4*)Wo, bo, out,
              (bx >> 3) << 5, (bx & 7) << 5, sm);
}

// ---------------------------------------------------------------------------
extern "C" void kernel_launch(void* const* d_in, const int* in_sizes, int n_in,
                              void* d_out, int out_size)
{
    const float* x  = (const float*)d_in[0];
    const float* Wq = (const float*)d_in[1];
    const float* bq = (const float*)d_in[2];
    const float* Wk = (const float*)d_in[3];
    const float* bk = (const float*)d_in[4];
    const float* Wv = (const float*)d_in[5];
    const float* bv = (const float*)d_in[6];
    const float* Wo = (const float*)d_in[7];
    const float* bo = (const float*)d_in[8];
    const float* ap = (const float*)d_in[9];
    float* out = (float*)d_out;

    k1_feat_vgemm<<<256, 256>>>(x, Wq, bq, Wk, bk, ap, Wv, bv);
    attn_kernel<<<128, 256>>>();
    k3_ogemm<<<128, 256>>>(Wo, bo, out);
}

// round 5
// speedup vs baseline: 1.4222x; 1.1764x over previous
#include <cuda_runtime.h>
#include <math.h>

#define Bx 4
#define Sx 128
#define Dx 256
#define Hx 8

static __device__ float  g_V [Bx*Sx*Dx];     // V = x@Wv.T + bv
static __device__ float  g_AO[Bx*Sx*Dx];     // attention output (pre-Wo)
static __device__ float  g_AB[Bx*Hx*Sx*6];   // per (b,h,i): A1,B1,A2,B2,A3,B3
static __device__ float4 g_CK[Bx*Hx*Sx];     // per (b,h,j): cos(k1..k3), pad

// ---------------------------------------------------------------------------
// GEMM core: C[m0+m][n0+n] = sum_k A[m][k]*B[n][k] + bias[n], K=256 (NT).
// 32m x 32n, 256 thr. Warp w: n-group ng=w&3 (8 n), k4-parity kp=w>>2.
// Thread: m=lane, 8 n, 2-way split accs (16 accs, dep chain 2/iter).
// As/Bs padded [32][33] f4: a-loads conflict-free (banks 4L..4L+3);
// b-loads warp-uniform broadcast (1 wavefront). Per warp-iter:
// 9 LDS + 32 FFMA, all offsets immediate -> FFMA-issue-bound.
// ---------------------------------------------------------------------------
__device__ __forceinline__ void gemm32x32(
    const float4* __restrict__ A4, const float4* __restrict__ B4,
    const float* __restrict__ bias, float* __restrict__ C,
    int m0, int n0, float* sm /* >= 8448 floats (33KB) */)
{
    float4* As = (float4*)sm;            // [32][33] float4
    float4* Bs = (float4*)sm + 32*33;    // [32][33] float4
    const int tid  = threadIdx.x;
    const int lane = tid & 31;
    const int w    = tid >> 5;
    const int ng   = w & 3;
    const int kp   = w >> 2;

    float acc[8][2];
#pragma unroll
    for (int j = 0; j < 8; j++) { acc[j][0] = 0.f; acc[j][1] = 0.f; }

    const float4* Ap = As + lane*33 + kp;
    const float4* Bp = Bs + (ng*8)*33 + kp;

    for (int kc = 0; kc < 2; kc++) {
#pragma unroll
        for (int t = 0; t < 4; t++) {
            const int idx = tid + (t << 8);
            const int r = idx >> 5, c = idx & 31;
            As[r*33 + c] = A4[(m0 + r)*64 + (kc << 5) + c];
            Bs[r*33 + c] = B4[(n0 + r)*64 + (kc << 5) + c];
        }
        __syncthreads();
#pragma unroll 4
        for (int k4 = 0; k4 < 16; k4++) {
            const float4 a = Ap[k4*2];
#pragma unroll
            for (int j = 0; j < 8; j++) {
                const float4 b = Bp[j*33 + k4*2];
                acc[j][0] = fmaf(a.x, b.x, acc[j][0]);
                acc[j][1] = fmaf(a.y, b.y, acc[j][1]);
                acc[j][0] = fmaf(a.z, b.z, acc[j][0]);
                acc[j][1] = fmaf(a.w, b.w, acc[j][1]);
            }
        }
        __syncthreads();
    }

    // cross-parity reduction (reuse As region; 128*17 floats, 17-pad = no conflicts)
    float* red = sm;
    if (kp == 1) {
#pragma unroll
        for (int j = 0; j < 8; j++) {
            red[(ng*32 + lane)*17 + j*2    ] = acc[j][0];
            red[(ng*32 + lane)*17 + j*2 + 1] = acc[j][1];
        }
    }
    __syncthreads();
    if (kp == 0) {
        const int n = n0 + ng*8;
        const float* rp = &red[(ng*32 + lane)*17];
        float4 o0, o1;
        o0.x = acc[0][0] + acc[0][1] + rp[0]  + rp[1]  + bias[n + 0];
        o0.y = acc[1][0] + acc[1][1] + rp[2]  + rp[3]  + bias[n + 1];
        o0.z = acc[2][0] + acc[2][1] + rp[4]  + rp[5]  + bias[n + 2];
        o0.w = acc[3][0] + acc[3][1] + rp[6]  + rp[7]  + bias[n + 3];
        o1.x = acc[4][0] + acc[4][1] + rp[8]  + rp[9]  + bias[n + 4];
        o1.y = acc[5][0] + acc[5][1] + rp[10] + rp[11] + bias[n + 5];
        o1.z = acc[6][0] + acc[6][1] + rp[12] + rp[13] + bias[n + 6];
        o1.w = acc[7][0] + acc[7][1] + rp[14] + rp[15] + bias[n + 7];
        *(float4*)&C[(m0 + lane)*256 + n    ] = o0;
        *(float4*)&C[(m0 + lane)*256 + n + 4] = o1;
    }
}

// ---------------------------------------------------------------------------
// Q/K features. Block = (b, 4 s-rows), 256 threads = 8 warps (warp = head).
// score(i,j) = prod_{w=1..3}( cos(th_w)cos(q_iw) - sin(th_w)sin(q_iw)cos(k_jw) )
// ---------------------------------------------------------------------------
__device__ void feat_body(
    const float* __restrict__ x,
    const float* __restrict__ Wq, const float* __restrict__ bq,
    const float* __restrict__ Wk, const float* __restrict__ bk,
    const float* __restrict__ ap, int bid, float* smem)
{
    float (*xs)[256] = (float(*)[256])smem;
    const int b  = bid >> 5;
    const int s0 = (bid & 31) << 2;
    const int tid = threadIdx.x;

    for (int t = tid; t < 1024; t += 256)
        xs[t >> 8][t & 255] = x[(b*Sx + s0 + (t >> 8))*Dx + (t & 255)];
    __syncthreads();

    const int h = tid >> 5, lane = tid & 31;
    float acc[4][8];
#pragma unroll
    for (int s = 0; s < 4; s++)
#pragma unroll
        for (int o = 0; o < 8; o++) acc[s][o] = 0.f;

    const float* wq = Wq + (h*32)*Dx;
    const float* wk = Wk + (h*32)*Dx;

#pragma unroll
    for (int c = 0; c < 8; c++) {
        const int d = lane + (c << 5);
        const float x0 = xs[0][d], x1 = xs[1][d], x2 = xs[2][d], x3 = xs[3][d];
#pragma unroll
        for (int o = 0; o < 4; o++) {
            const float wv = wq[o*Dx + d];
            acc[0][o] = fmaf(x0, wv, acc[0][o]);
            acc[1][o] = fmaf(x1, wv, acc[1][o]);
            acc[2][o] = fmaf(x2, wv, acc[2][o]);
            acc[3][o] = fmaf(x3, wv, acc[3][o]);
        }
#pragma unroll
        for (int o = 0; o < 4; o++) {
            const float wv = wk[o*Dx + d];
            acc[0][4+o] = fmaf(x0, wv, acc[0][4+o]);
            acc[1][4+o] = fmaf(x1, wv, acc[1][4+o]);
            acc[2][4+o] = fmaf(x2, wv, acc[2][4+o]);
            acc[3][4+o] = fmaf(x3, wv, acc[3][4+o]);
        }
    }

#pragma unroll
    for (int s = 0; s < 4; s++)
#pragma unroll
        for (int o = 0; o < 8; o++) {
            float v = acc[s][o];
            v += __shfl_xor_sync(0xffffffffu, v, 16);
            v += __shfl_xor_sync(0xffffffffu, v, 8);
            v += __shfl_xor_sync(0xffffffffu, v, 4);
            v += __shfl_xor_sync(0xffffffffu, v, 2);
            v += __shfl_xor_sync(0xffffffffu, v, 1);
            acc[s][o] = v;
        }

    if (lane < 8) {
        const int sp = lane >> 1;
        const int side = lane & 1;
        const float* bias = side ? bk : bq;
        float vals[4];
#pragma unroll
        for (int wv = 0; wv < 4; wv++)
            vals[wv] = acc[sp][side*4 + wv] + bias[h*32 + wv];

        const float mn = fminf(fminf(vals[0], vals[1]), fminf(vals[2], vals[3]));
        const float mx = fmaxf(fmaxf(vals[0], vals[1]), fmaxf(vals[2], vals[3]));
        const float sc = 3.14159265358979323846f / (mx - mn + 1e-8f);
        const int idx = (b*Hx + h)*Sx + s0 + sp;

        if (side == 0) {
#pragma unroll
            for (int wv = 1; wv < 4; wv++) {
                const float ang = (vals[wv] - mn) * sc;
                float sn, cs;
                sincosf(ang, &sn, &cs);
                const float th = ap[wv];
                g_AB[idx*6 + (wv-1)*2 + 0] = cosf(th) * cs;
                g_AB[idx*6 + (wv-1)*2 + 1] = sinf(th) * sn;
            }
        } else {
            float c1 = cosf((vals[1] - mn) * sc);
            float c2 = cosf((vals[2] - mn) * sc);
            float c3 = cosf((vals[3] - mn) * sc);
            g_CK[idx] = make_float4(c1, c2, c3, 0.f);
        }
    }
}

// ---------------------------------------------------------------------------
// Kernel 1: V-GEMM (128 blocks) + qk features (128 blocks), 256 thr each.
// ---------------------------------------------------------------------------
__global__ void __launch_bounds__(256) k1_feat_vgemm(
    const float* __restrict__ x,
    const float* __restrict__ Wq, const float* __restrict__ bq,
    const float* __restrict__ Wk, const float* __restrict__ bk,
    const float* __restrict__ ap,
    const float* __restrict__ Wv, const float* __restrict__ bv)
{
    __shared__ float sm[8448];    // 33KB
    const int bx = blockIdx.x;
    if (bx < 128) {
        gemm32x32((const float4*)x, (const float4*)Wv, bv, g_V,
                  (bx >> 3) << 5, (bx & 7) << 5, sm);
    } else {
        feat_body(x, Wq, bq, Wk, bk, ap, bx - 128, sm);
    }
}

// ---------------------------------------------------------------------------
// Kernel 2: attention. 128 blocks = (bh, 32-row i-group), 256 threads.
// Phase 1: each exp computed once -> E[j][i] (padded), per-i sums.
// Phase 2: o[i][d4] = sum_j E[j][i] * V[j][d4], then scale by 1/sum.
// Scores bounded (|s|<=0.177) -> no max subtraction needed.
// ---------------------------------------------------------------------------
__global__ void __launch_bounds__(256) attn_kernel()
{
    const int bx = blockIdx.x;
    const int ig = bx & 3;
    const int bh = bx >> 2;
    const int b = bh >> 3, h = bh & 7;

    __shared__ float4 Vs[1024];      // [j][p], p = d4 group 0..7
    __shared__ float4 CKs[128];
    __shared__ float  E[128*33];     // [j][il], pad 33
    __shared__ float  Psum[32*9];    // [il][jg], pad 9
    __shared__ float  Sinv[32];

    const int tid = threadIdx.x;
    const float4* V4 = (const float4*)g_V;
#pragma unroll
    for (int t = 0; t < 4; t++) {
        const int idx = tid + (t << 8);
        const int j = idx >> 3, p = idx & 7;
        Vs[idx] = V4[(b*Sx + j)*64 + h*8 + p];
    }
    if (tid < 128) CKs[tid] = g_CK[bh*Sx + tid];
    __syncthreads();

    const int il = tid & 31;
    const int i  = (ig << 5) + il;

    // phase 1: jg = tid>>5 handles 16 j's
    {
        const int jg = tid >> 5;
        const float* ab = &g_AB[(bh*Sx + i)*6];
        const float A1 = ab[0], B1 = ab[1];
        const float A2 = ab[2], B2 = ab[3];
        const float A3 = ab[4], B3 = ab[5];
        const float SCALE = 0.17677669529663687f; // 1/sqrt(32)
        float s = 0.f;
#pragma unroll
        for (int jj = 0; jj < 16; jj++) {
            const int j = (jg << 4) + jj;
            const float4 ck = CKs[j];
            const float sc = (A1 - B1*ck.x) * (A2 - B2*ck.y) * (A3 - B3*ck.z);
            const float e = __expf(sc * SCALE);
            E[j*33 + il] = e;
            s += e;
        }
        Psum[il*9 + jg] = s;
    }
    __syncthreads();
    if (tid < 32) {
        float s = 0.f;
#pragma unroll
        for (int jg = 0; jg < 8; jg++) s += Psum[tid*9 + jg];
        Sinv[tid] = 1.0f / s;
    }
    __syncthreads();

    // phase 2: p = tid>>5 owns one float4 dim-group (broadcast V loads)
    {
        const int p = tid >> 5;
        float4 o = make_float4(0.f, 0.f, 0.f, 0.f);
#pragma unroll 8
        for (int j = 0; j < 128; j++) {
            const float e = E[j*33 + il];
            const float4 v = Vs[(j << 3) + p];
            o.x = fmaf(e, v.x, o.x);
            o.y = fmaf(e, v.y, o.y);
            o.z = fmaf(e, v.z, o.z);
            o.w = fmaf(e, v.w, o.w);
        }
        const float inv = Sinv[il];
        o.x *= inv; o.y *= inv; o.z *= inv; o.w *= inv;
        ((float4*)g_AO)[(b*Sx + i)*64 + h*8 + p] = o;
    }
}

// ---------------------------------------------------------------------------
// Kernel 3: out = g_AO @ Wo.T + bo  (128 blocks)
// ---------------------------------------------------------------------------
__global__ void __launch_bounds__(256) k3_ogemm(
    const float* __restrict__ Wo, const float* __restrict__ bo,
    float* __restrict__ out)
{
    __shared__ float sm[8448];
    const int bx = blockIdx.x;
    gemm32x32((const float4*)g_AO, (const float4*)Wo, bo, out,
              (bx >> 3) << 5, (bx & 7) << 5, sm);
}

// ---------------------------------------------------------------------------
extern "C" void kernel_launch(void* const* d_in, const int* in_sizes, int n_in,
                              void* d_out, int out_size)
{
    const float* x  = (const float*)d_in[0];
    const float* Wq = (const float*)d_in[1];
    const float* bq = (const float*)d_in[2];
    const float* Wk = (const float*)d_in[3];
    const float* bk = (const float*)d_in[4];
    const float* Wv = (const float*)d_in[5];
    const float* bv = (const float*)d_in[6];
    const float* Wo = (const float*)d_in[7];
    const float* bo = (const float*)d_in[8];
    const float* ap = (const float*)d_in[9];
    float* out = (float*)d_out;

    k1_feat_vgemm<<<256, 256>>>(x, Wq, bq, Wk, bk, ap, Wv, bv);
    attn_kernel<<<128, 256>>>();
    k3_ogemm<<<128, 256>>>(Wo, bo, out);
}